// round 1
// baseline (speedup 1.0000x reference)
#include <cuda_runtime.h>
#include <cstddef>

// Problem constants (fixed by the reference)
#define B_    4096
#define NIN_  512
#define L_    16
#define N_    512
#define K_    32
#define NOUT_ 256
#define TOTAL_ (NIN_ + L_ * N_)   // 8704
#define BQ_   (B_ / 4)            // 1024 float4 quads across batch

// Activation buffer, transposed: g_buf[feature * B + batch]
// 8704 * 4096 * 4 B = ~142.6 MB static device scratch (allowed).
__device__ float g_buf[(size_t)TOTAL_ * B_];

// ---------------------------------------------------------------------------
// Transpose x (B, NIN) row-major -> g_buf[f * B + b]
// ---------------------------------------------------------------------------
__global__ void __launch_bounds__(1024) transpose_in_kernel(const float* __restrict__ x) {
    __shared__ float tile[32][33];
    int f0 = blockIdx.x * 32;
    int b0 = blockIdx.y * 32;
    // coalesced read along features
    tile[threadIdx.y][threadIdx.x] = x[(size_t)(b0 + threadIdx.y) * NIN_ + (f0 + threadIdx.x)];
    __syncthreads();
    // coalesced write along batch
    g_buf[(size_t)(f0 + threadIdx.y) * B_ + (b0 + threadIdx.x)] = tile[threadIdx.x][threadIdx.y];
}

__device__ __forceinline__ float sigmoidf_(float v) {
    return 1.0f / (1.0f + __expf(-v));
}

// ---------------------------------------------------------------------------
// One sparse layer: out[n, :] = sigmoid( sum_k buf[idx[n,k], :] * W[n,k] + b[n] )
// block: (32, 8) -> 32 batch-quads (128 batch elems) x 8 neurons
// grid:  (BQ/32 = 32, N/8 = 64)
// ---------------------------------------------------------------------------
__global__ void __launch_bounds__(256) layer_kernel(
    const float* __restrict__ W,     // (N, K) for this layer
    const float* __restrict__ bias,  // (N,)
    const int*   __restrict__ idx,   // (N, K)
    int out_base)                    // NIN + l*N
{
    __shared__ int   s_idx[8][K_];
    __shared__ float s_w[8][K_];
    const int tx = threadIdx.x, ty = threadIdx.y;
    const int n = blockIdx.y * 8 + ty;

    s_idx[ty][tx] = idx[n * K_ + tx];
    s_w[ty][tx]   = W[n * K_ + tx];
    __syncthreads();

    const int q = blockIdx.x * 32 + tx;
    const float4* __restrict__ buf4 = reinterpret_cast<const float4*>(g_buf);

    float4 acc = make_float4(0.f, 0.f, 0.f, 0.f);
#pragma unroll
    for (int k = 0; k < K_; ++k) {
        const int   f = s_idx[ty][k];
        const float w = s_w[ty][k];
        const float4 v = buf4[(size_t)f * BQ_ + q];
        acc.x = fmaf(w, v.x, acc.x);
        acc.y = fmaf(w, v.y, acc.y);
        acc.z = fmaf(w, v.z, acc.z);
        acc.w = fmaf(w, v.w, acc.w);
    }

    const float bb = bias[n];
    float4 r;
    r.x = sigmoidf_(acc.x + bb);
    r.y = sigmoidf_(acc.y + bb);
    r.z = sigmoidf_(acc.z + bb);
    r.w = sigmoidf_(acc.w + bb);

    reinterpret_cast<float4*>(g_buf)[(size_t)(out_base + n) * BQ_ + q] = r;
}

// ---------------------------------------------------------------------------
// Output layer: out[b, o] = sigmoid( sum_k buf[idx_out[o,k], b] * W_out[o,k] + b_out[o] )
// Same gather structure; writes row-major (B, NOUT) output.
// ---------------------------------------------------------------------------
__global__ void __launch_bounds__(256) out_kernel(
    const float* __restrict__ W_out,   // (NOUT, K)
    const float* __restrict__ b_out,   // (NOUT,)
    const int*   __restrict__ idx_out, // (NOUT, K)
    float* __restrict__ out)           // (B, NOUT)
{
    __shared__ int   s_idx[8][K_];
    __shared__ float s_w[8][K_];
    const int tx = threadIdx.x, ty = threadIdx.y;
    const int o = blockIdx.y * 8 + ty;

    s_idx[ty][tx] = idx_out[o * K_ + tx];
    s_w[ty][tx]   = W_out[o * K_ + tx];
    __syncthreads();

    const int q = blockIdx.x * 32 + tx;
    const float4* __restrict__ buf4 = reinterpret_cast<const float4*>(g_buf);

    float4 acc = make_float4(0.f, 0.f, 0.f, 0.f);
#pragma unroll
    for (int k = 0; k < K_; ++k) {
        const int   f = s_idx[ty][k];
        const float w = s_w[ty][k];
        const float4 v = buf4[(size_t)f * BQ_ + q];
        acc.x = fmaf(w, v.x, acc.x);
        acc.y = fmaf(w, v.y, acc.y);
        acc.z = fmaf(w, v.z, acc.z);
        acc.w = fmaf(w, v.w, acc.w);
    }

    const float bb = b_out[o];
    const int b0 = q * 4;
    out[(size_t)(b0 + 0) * NOUT_ + o] = sigmoidf_(acc.x + bb);
    out[(size_t)(b0 + 1) * NOUT_ + o] = sigmoidf_(acc.y + bb);
    out[(size_t)(b0 + 2) * NOUT_ + o] = sigmoidf_(acc.z + bb);
    out[(size_t)(b0 + 3) * NOUT_ + o] = sigmoidf_(acc.w + bb);
}

// ---------------------------------------------------------------------------
// kernel_launch: inputs in metadata order:
//   0: x     (B, NIN)   f32
//   1: W     (L, N, K)  f32
//   2: b     (L, N)     f32
//   3: W_out (NOUT, K)  f32
//   4: b_out (NOUT,)    f32
//   5: idx     (L, N, K) i32
//   6: idx_out (NOUT, K) i32
// ---------------------------------------------------------------------------
extern "C" void kernel_launch(void* const* d_in, const int* in_sizes, int n_in,
                              void* d_out, int out_size) {
    const float* x     = (const float*)d_in[0];
    const float* W     = (const float*)d_in[1];
    const float* b     = (const float*)d_in[2];
    const float* W_out = (const float*)d_in[3];
    const float* b_out = (const float*)d_in[4];
    const int*   idx     = (const int*)d_in[5];
    const int*   idx_out = (const int*)d_in[6];
    float* out = (float*)d_out;

    // 1) transpose input into feature-major buffer
    {
        dim3 blk(32, 32);
        dim3 grd(NIN_ / 32, B_ / 32);
        transpose_in_kernel<<<grd, blk>>>(x);
    }

    // 2) 16 sparse layers, sequential (true data dependency)
    {
        dim3 blk(32, 8);
        dim3 grd(BQ_ / 32, N_ / 8);
        for (int l = 0; l < L_; ++l) {
            layer_kernel<<<grd, blk>>>(W + (size_t)l * N_ * K_,
                                       b + (size_t)l * N_,
                                       idx + (size_t)l * N_ * K_,
                                       NIN_ + l * N_);
        }
    }

    // 3) output layer
    {
        dim3 blk(32, 8);
        dim3 grd(BQ_ / 32, NOUT_ / 8);
        out_kernel<<<grd, blk>>>(W_out, b_out, idx_out, out);
    }
}

// round 2
// speedup vs baseline: 1.5891x; 1.5891x over previous
#include <cuda_runtime.h>
#include <cuda_fp16.h>
#include <cstddef>

// Problem constants (fixed by the reference)
#define B_    4096
#define NIN_  512
#define L_    16
#define N_    512
#define K_    32
#define NOUT_ 256
#define TOTAL_ (NIN_ + L_ * N_)   // 8704
#define BG_   (B_ / 8)            // 512 groups of 8 batch elems (16B of half)

// Activation buffer, transposed + fp16: g_buf[feature * B + batch]
// 8704 * 4096 * 2 B = ~71 MB static device scratch.
__device__ __half g_buf[(size_t)TOTAL_ * B_];

// ---------------------------------------------------------------------------
// Transpose x (B, NIN) f32 row-major -> g_buf[f * B + b] as half
// ---------------------------------------------------------------------------
__global__ void __launch_bounds__(1024) transpose_in_kernel(const float* __restrict__ x) {
    __shared__ float tile[32][33];
    int f0 = blockIdx.x * 32;
    int b0 = blockIdx.y * 32;
    tile[threadIdx.y][threadIdx.x] = x[(size_t)(b0 + threadIdx.y) * NIN_ + (f0 + threadIdx.x)];
    __syncthreads();
    g_buf[(size_t)(f0 + threadIdx.y) * B_ + (b0 + threadIdx.x)] =
        __float2half(tile[threadIdx.x][threadIdx.y]);
}

__device__ __forceinline__ float sigmoidf_(float v) {
    return 1.0f / (1.0f + __expf(-v));
}

// ---------------------------------------------------------------------------
// One sparse layer: out[n, :] = sigmoid( sum_k buf[idx[n,k], :] * W[n,k] + b[n] )
// block: (32, 8) -> 32 groups of 8 batch (256 batch elems) x 8 neurons
// grid:  (BG/32 = 16, N/8 = 64)
// Each thread: 8 batch elems, K=32 gathered uint4 (8 halves) loads.
// ---------------------------------------------------------------------------
__global__ void __launch_bounds__(256) layer_kernel(
    const float* __restrict__ W,     // (N, K) for this layer
    const float* __restrict__ bias,  // (N,)
    const int*   __restrict__ idx,   // (N, K)
    int out_base)                    // NIN + l*N
{
    __shared__ int   s_idx[8][K_];
    __shared__ float s_w[8][K_];
    const int tx = threadIdx.x, ty = threadIdx.y;
    const int n = blockIdx.y * 8 + ty;

    s_idx[ty][tx] = idx[n * K_ + tx];
    s_w[ty][tx]   = W[n * K_ + tx];
    __syncthreads();

    const int q = blockIdx.x * 32 + tx;                 // group of 8 batch elems
    const uint4* __restrict__ buf16 = reinterpret_cast<const uint4*>(g_buf);

    float a0 = 0.f, a1 = 0.f, a2 = 0.f, a3 = 0.f;
    float a4 = 0.f, a5 = 0.f, a6 = 0.f, a7 = 0.f;

#pragma unroll
    for (int k = 0; k < K_; ++k) {
        const int   f = s_idx[ty][k];
        const float w = s_w[ty][k];
        const uint4 v = buf16[(size_t)f * BG_ + q];
        const __half2* h = reinterpret_cast<const __half2*>(&v);
        float2 p0 = __half22float2(h[0]);
        float2 p1 = __half22float2(h[1]);
        float2 p2 = __half22float2(h[2]);
        float2 p3 = __half22float2(h[3]);
        a0 = fmaf(w, p0.x, a0);  a1 = fmaf(w, p0.y, a1);
        a2 = fmaf(w, p1.x, a2);  a3 = fmaf(w, p1.y, a3);
        a4 = fmaf(w, p2.x, a4);  a5 = fmaf(w, p2.y, a5);
        a6 = fmaf(w, p3.x, a6);  a7 = fmaf(w, p3.y, a7);
    }

    const float bb = bias[n];
    __half2 r0 = __floats2half2_rn(sigmoidf_(a0 + bb), sigmoidf_(a1 + bb));
    __half2 r1 = __floats2half2_rn(sigmoidf_(a2 + bb), sigmoidf_(a3 + bb));
    __half2 r2 = __floats2half2_rn(sigmoidf_(a4 + bb), sigmoidf_(a5 + bb));
    __half2 r3 = __floats2half2_rn(sigmoidf_(a6 + bb), sigmoidf_(a7 + bb));

    uint4 o;
    o.x = *reinterpret_cast<unsigned*>(&r0);
    o.y = *reinterpret_cast<unsigned*>(&r1);
    o.z = *reinterpret_cast<unsigned*>(&r2);
    o.w = *reinterpret_cast<unsigned*>(&r3);
    reinterpret_cast<uint4*>(g_buf)[(size_t)(out_base + n) * BG_ + q] = o;
}

// ---------------------------------------------------------------------------
// Output layer: out[b, o] = sigmoid( sum_k buf[idx_out[o,k], b] * W_out[o,k] + b_out[o] )
// Gathers like layer_kernel, then smem-transposes so each thread writes one
// full 32-byte sector (8 consecutive f32 outputs for one batch row).
// block: (32, 8); grid: (BG/32 = 16, NOUT/8 = 32)
// ---------------------------------------------------------------------------
__global__ void __launch_bounds__(256) out_kernel(
    const float* __restrict__ W_out,   // (NOUT, K)
    const float* __restrict__ b_out,   // (NOUT,)
    const int*   __restrict__ idx_out, // (NOUT, K)
    float* __restrict__ out)           // (B, NOUT)
{
    __shared__ int   s_idx[8][K_];
    __shared__ float s_w[8][K_];
    __shared__ float tile[8][256];     // [neuron][batch within block]
    const int tx = threadIdx.x, ty = threadIdx.y;
    const int o0 = blockIdx.y * 8;
    const int o = o0 + ty;

    s_idx[ty][tx] = idx_out[o * K_ + tx];
    s_w[ty][tx]   = W_out[o * K_ + tx];
    __syncthreads();

    const int q = blockIdx.x * 32 + tx;
    const uint4* __restrict__ buf16 = reinterpret_cast<const uint4*>(g_buf);

    float a0 = 0.f, a1 = 0.f, a2 = 0.f, a3 = 0.f;
    float a4 = 0.f, a5 = 0.f, a6 = 0.f, a7 = 0.f;

#pragma unroll
    for (int k = 0; k < K_; ++k) {
        const int   f = s_idx[ty][k];
        const float w = s_w[ty][k];
        const uint4 v = buf16[(size_t)f * BG_ + q];
        const __half2* h = reinterpret_cast<const __half2*>(&v);
        float2 p0 = __half22float2(h[0]);
        float2 p1 = __half22float2(h[1]);
        float2 p2 = __half22float2(h[2]);
        float2 p3 = __half22float2(h[3]);
        a0 = fmaf(w, p0.x, a0);  a1 = fmaf(w, p0.y, a1);
        a2 = fmaf(w, p1.x, a2);  a3 = fmaf(w, p1.y, a3);
        a4 = fmaf(w, p2.x, a4);  a5 = fmaf(w, p2.y, a5);
        a6 = fmaf(w, p3.x, a6);  a7 = fmaf(w, p3.y, a7);
    }

    const float bb = b_out[o];
    const int bl = tx * 8;             // local batch base within block
    tile[ty][bl + 0] = sigmoidf_(a0 + bb);
    tile[ty][bl + 1] = sigmoidf_(a1 + bb);
    tile[ty][bl + 2] = sigmoidf_(a2 + bb);
    tile[ty][bl + 3] = sigmoidf_(a3 + bb);
    tile[ty][bl + 4] = sigmoidf_(a4 + bb);
    tile[ty][bl + 5] = sigmoidf_(a5 + bb);
    tile[ty][bl + 6] = sigmoidf_(a6 + bb);
    tile[ty][bl + 7] = sigmoidf_(a7 + bb);
    __syncthreads();

    // Write phase: thread t -> batch row (b0 + t), 8 consecutive outputs (32B sector)
    const int t = ty * 32 + tx;
    const int b = blockIdx.x * 256 + t;
    float4 w0, w1;
    w0.x = tile[0][t]; w0.y = tile[1][t]; w0.z = tile[2][t]; w0.w = tile[3][t];
    w1.x = tile[4][t]; w1.y = tile[5][t]; w1.z = tile[6][t]; w1.w = tile[7][t];
    float4* dst = reinterpret_cast<float4*>(out + (size_t)b * NOUT_ + o0);
    dst[0] = w0;
    dst[1] = w1;
}

// ---------------------------------------------------------------------------
// kernel_launch: inputs in metadata order:
//   0: x (B,NIN) f32   1: W (L,N,K) f32   2: b (L,N) f32
//   3: W_out (NOUT,K) f32   4: b_out (NOUT,) f32
//   5: idx (L,N,K) i32      6: idx_out (NOUT,K) i32
// ---------------------------------------------------------------------------
extern "C" void kernel_launch(void* const* d_in, const int* in_sizes, int n_in,
                              void* d_out, int out_size) {
    const float* x     = (const float*)d_in[0];
    const float* W     = (const float*)d_in[1];
    const float* b     = (const float*)d_in[2];
    const float* W_out = (const float*)d_in[3];
    const float* b_out = (const float*)d_in[4];
    const int*   idx     = (const int*)d_in[5];
    const int*   idx_out = (const int*)d_in[6];
    float* out = (float*)d_out;

    // 1) transpose input into feature-major half buffer
    {
        dim3 blk(32, 32);
        dim3 grd(NIN_ / 32, B_ / 32);
        transpose_in_kernel<<<grd, blk>>>(x);
    }

    // 2) 16 sparse layers, sequential (true data dependency)
    {
        dim3 blk(32, 8);
        dim3 grd(BG_ / 32, N_ / 8);
        for (int l = 0; l < L_; ++l) {
            layer_kernel<<<grd, blk>>>(W + (size_t)l * N_ * K_,
                                       b + (size_t)l * N_,
                                       idx + (size_t)l * N_ * K_,
                                       NIN_ + l * N_);
        }
    }

    // 3) output layer
    {
        dim3 blk(32, 8);
        dim3 grd(BG_ / 32, NOUT_ / 8);
        out_kernel<<<grd, blk>>>(W_out, b_out, idx_out, out);
    }
}

// round 3
// speedup vs baseline: 1.7899x; 1.1263x over previous
#include <cuda_runtime.h>
#include <cuda_fp16.h>
#include <cstddef>

// Problem constants (fixed by the reference)
#define B_    4096
#define NIN_  512
#define L_    16
#define N_    512
#define K_    32
#define NOUT_ 256
#define TOTAL_ (NIN_ + L_ * N_)   // 8704
#define BG_   (B_ / 8)            // 512 groups of 8 halves (16B) across batch

// Activation buffer, transposed + fp16: g_buf[feature * B + batch]
// 8704 * 4096 * 2 B = ~71 MB static device scratch.
__device__ __half g_buf[(size_t)TOTAL_ * B_];

// ---------------------------------------------------------------------------
// Transpose x (B, NIN) f32 row-major -> g_buf[f * B + b] as half
// ---------------------------------------------------------------------------
__global__ void __launch_bounds__(1024) transpose_in_kernel(const float* __restrict__ x) {
    __shared__ float tile[32][33];
    int f0 = blockIdx.x * 32;
    int b0 = blockIdx.y * 32;
    tile[threadIdx.y][threadIdx.x] = x[(size_t)(b0 + threadIdx.y) * NIN_ + (f0 + threadIdx.x)];
    __syncthreads();
    g_buf[(size_t)(f0 + threadIdx.y) * B_ + (b0 + threadIdx.x)] =
        __float2half(tile[threadIdx.x][threadIdx.y]);
}

__device__ __forceinline__ float sigmoidf_(float v) {
    return 1.0f / (1.0f + __expf(-v));
}

__device__ __forceinline__ void fma8_(float* a, float w, uint4 v) {
    const __half2* h = reinterpret_cast<const __half2*>(&v);
    float2 p0 = __half22float2(h[0]);
    float2 p1 = __half22float2(h[1]);
    float2 p2 = __half22float2(h[2]);
    float2 p3 = __half22float2(h[3]);
    a[0] = fmaf(w, p0.x, a[0]);  a[1] = fmaf(w, p0.y, a[1]);
    a[2] = fmaf(w, p1.x, a[2]);  a[3] = fmaf(w, p1.y, a[3]);
    a[4] = fmaf(w, p2.x, a[4]);  a[5] = fmaf(w, p2.y, a[5]);
    a[6] = fmaf(w, p3.x, a[6]);  a[7] = fmaf(w, p3.y, a[7]);
}

// ---------------------------------------------------------------------------
// One sparse layer: out[n, :] = sigmoid( sum_k buf[idx[n,k], :] * W[n,k] + b[n] )
// block: (32, 8); each thread: 16 batch elems (groups q and q+256)
// grid:  (8, 64) = 512 blocks -> single resident wave, uniform work
// ---------------------------------------------------------------------------
__global__ void __launch_bounds__(256, 4) layer_kernel(
    const float* __restrict__ W,     // (N, K) for this layer
    const float* __restrict__ bias,  // (N,)
    const int*   __restrict__ idx,   // (N, K)
    int out_base)                    // NIN + l*N
{
    __shared__ int   s_idx[8][K_];
    __shared__ float s_w[8][K_];
    const int tx = threadIdx.x, ty = threadIdx.y;
    const int n = blockIdx.y * 8 + ty;

    s_idx[ty][tx] = idx[n * K_ + tx];
    s_w[ty][tx]   = W[n * K_ + tx];
    __syncthreads();

    const int q = blockIdx.x * 32 + tx;   // [0, 256): handles groups q and q+256
    const uint4* __restrict__ buf16 = reinterpret_cast<const uint4*>(g_buf);

    float a[16];
#pragma unroll
    for (int i = 0; i < 16; ++i) a[i] = 0.f;

#pragma unroll
    for (int k = 0; k < K_; ++k) {
        const int   f = s_idx[ty][k];
        const float w = s_w[ty][k];
        const size_t base = (size_t)f * BG_ + q;
        uint4 v0 = buf16[base];
        uint4 v1 = buf16[base + 256];
        fma8_(a,     w, v0);
        fma8_(a + 8, w, v1);
    }

    const float bb = bias[n];
    uint4 o0, o1;
    {
        __half2 r0 = __floats2half2_rn(sigmoidf_(a[0] + bb), sigmoidf_(a[1] + bb));
        __half2 r1 = __floats2half2_rn(sigmoidf_(a[2] + bb), sigmoidf_(a[3] + bb));
        __half2 r2 = __floats2half2_rn(sigmoidf_(a[4] + bb), sigmoidf_(a[5] + bb));
        __half2 r3 = __floats2half2_rn(sigmoidf_(a[6] + bb), sigmoidf_(a[7] + bb));
        o0.x = *reinterpret_cast<unsigned*>(&r0);
        o0.y = *reinterpret_cast<unsigned*>(&r1);
        o0.z = *reinterpret_cast<unsigned*>(&r2);
        o0.w = *reinterpret_cast<unsigned*>(&r3);
    }
    {
        __half2 r0 = __floats2half2_rn(sigmoidf_(a[8]  + bb), sigmoidf_(a[9]  + bb));
        __half2 r1 = __floats2half2_rn(sigmoidf_(a[10] + bb), sigmoidf_(a[11] + bb));
        __half2 r2 = __floats2half2_rn(sigmoidf_(a[12] + bb), sigmoidf_(a[13] + bb));
        __half2 r3 = __floats2half2_rn(sigmoidf_(a[14] + bb), sigmoidf_(a[15] + bb));
        o1.x = *reinterpret_cast<unsigned*>(&r0);
        o1.y = *reinterpret_cast<unsigned*>(&r1);
        o1.z = *reinterpret_cast<unsigned*>(&r2);
        o1.w = *reinterpret_cast<unsigned*>(&r3);
    }
    const size_t obase = (size_t)(out_base + n) * BG_ + q;
    reinterpret_cast<uint4*>(g_buf)[obase]       = o0;
    reinterpret_cast<uint4*>(g_buf)[obase + 256] = o1;
}

// ---------------------------------------------------------------------------
// Output layer: out[b, o] = sigmoid( sum_k buf[idx_out[o,k], b] * W_out[o,k] + b_out[o] )
// Gathers 8 batch per thread, smem-transpose, 32B-sector stores.
// block: (32, 8); grid: (BG/32 = 16, NOUT/8 = 32)
// ---------------------------------------------------------------------------
__global__ void __launch_bounds__(256) out_kernel(
    const float* __restrict__ W_out,   // (NOUT, K)
    const float* __restrict__ b_out,   // (NOUT,)
    const int*   __restrict__ idx_out, // (NOUT, K)
    float* __restrict__ out)           // (B, NOUT)
{
    __shared__ int   s_idx[8][K_];
    __shared__ float s_w[8][K_];
    __shared__ float tile[8][256];     // [neuron][batch within block]
    const int tx = threadIdx.x, ty = threadIdx.y;
    const int o0 = blockIdx.y * 8;
    const int o = o0 + ty;

    s_idx[ty][tx] = idx_out[o * K_ + tx];
    s_w[ty][tx]   = W_out[o * K_ + tx];
    __syncthreads();

    const int q = blockIdx.x * 32 + tx;
    const uint4* __restrict__ buf16 = reinterpret_cast<const uint4*>(g_buf);

    float a[8];
#pragma unroll
    for (int i = 0; i < 8; ++i) a[i] = 0.f;

#pragma unroll
    for (int k = 0; k < K_; ++k) {
        const int   f = s_idx[ty][k];
        const float w = s_w[ty][k];
        uint4 v = buf16[(size_t)f * BG_ + q];
        fma8_(a, w, v);
    }

    const float bb = b_out[o];
    const int bl = tx * 8;
#pragma unroll
    for (int i = 0; i < 8; ++i) tile[ty][bl + i] = sigmoidf_(a[i] + bb);
    __syncthreads();

    const int t = ty * 32 + tx;
    const int b = blockIdx.x * 256 + t;
    float4 w0, w1;
    w0.x = tile[0][t]; w0.y = tile[1][t]; w0.z = tile[2][t]; w0.w = tile[3][t];
    w1.x = tile[4][t]; w1.y = tile[5][t]; w1.z = tile[6][t]; w1.w = tile[7][t];
    float4* dst = reinterpret_cast<float4*>(out + (size_t)b * NOUT_ + o0);
    dst[0] = w0;
    dst[1] = w1;
}

// ---------------------------------------------------------------------------
// kernel_launch: inputs in metadata order:
//   0: x (B,NIN) f32   1: W (L,N,K) f32   2: b (L,N) f32
//   3: W_out (NOUT,K) f32   4: b_out (NOUT,) f32
//   5: idx (L,N,K) i32      6: idx_out (NOUT,K) i32
// ---------------------------------------------------------------------------
extern "C" void kernel_launch(void* const* d_in, const int* in_sizes, int n_in,
                              void* d_out, int out_size) {
    const float* x     = (const float*)d_in[0];
    const float* W     = (const float*)d_in[1];
    const float* b     = (const float*)d_in[2];
    const float* W_out = (const float*)d_in[3];
    const float* b_out = (const float*)d_in[4];
    const int*   idx     = (const int*)d_in[5];
    const int*   idx_out = (const int*)d_in[6];
    float* out = (float*)d_out;

    // 1) transpose input into feature-major half buffer
    {
        dim3 blk(32, 32);
        dim3 grd(NIN_ / 32, B_ / 32);
        transpose_in_kernel<<<grd, blk>>>(x);
    }

    // 2) 16 sparse layers, sequential (true data dependency)
    {
        dim3 blk(32, 8);
        dim3 grd(8, N_ / 8);   // 512 blocks: single resident wave
        for (int l = 0; l < L_; ++l) {
            layer_kernel<<<grd, blk>>>(W + (size_t)l * N_ * K_,
                                       b + (size_t)l * N_,
                                       idx + (size_t)l * N_ * K_,
                                       NIN_ + l * N_);
        }
    }

    // 3) output layer
    {
        dim3 blk(32, 8);
        dim3 grd(BG_ / 32, NOUT_ / 8);
        out_kernel<<<grd, blk>>>(W_out, b_out, idx_out, out);
    }
}